// round 13
// baseline (speedup 1.0000x reference)
#include <cuda_runtime.h>
#include <math.h>
#include <stdint.h>

// Problem constants
#define TDIM 4096          // B*S tokens
#define HDIM 1024          // hidden
#define EDIM 8             // experts
#define FDIM 2048          // ffn
#define KSEL 2             // top-k
#define NROWS (TDIM*KSEL)  // 8192 dispatch rows

// ==================== device scratch (allocation-free) ====================
__device__ float g_glu[(size_t)NROWS * FDIM];    // GLU activations (list order)
__device__ float g_pairs[(size_t)NROWS * HDIM];  // expert outputs per (token,slot)
__device__ int   g_eid[NROWS];
__device__ float g_gate[NROWS];
__device__ int   g_list[NROWS];
__device__ int   g_freq[EDIM];
__device__ int   g_cursor[EDIM];
__device__ int   g_offsets[EDIM + 1];
__device__ float g_psum[EDIM];
__device__ float g_lsesq;

// ==================== PTX helpers (sm_80-baseline features only) ====================
__device__ __forceinline__ uint32_t smem_u32(const void* p) {
    uint32_t a;
    asm("{ .reg .u64 t; cvta.to.shared.u64 t, %1; cvt.u32.u64 %0, t; }" : "=r"(a) : "l"(p));
    return a;
}
__device__ __forceinline__ void cp16(uint32_t dst, const void* src) {
    asm volatile("cp.async.cg.shared.global [%0], [%1], 16;" :: "r"(dst), "l"(src));
}
#define CP_COMMIT() asm volatile("cp.async.commit_group;" ::: "memory")
#define CP_WAIT1()  asm volatile("cp.async.wait_group 1;" ::: "memory")
#define CP_WAIT0()  asm volatile("cp.async.wait_group 0;" ::: "memory")

__device__ __forceinline__ uint32_t f2tf32(float f) {
    uint32_t r;
    asm("cvt.rna.tf32.f32 %0, %1;" : "=r"(r) : "f"(f));
    return r;
}
__device__ __forceinline__ void mma_tf32(float* d, const uint32_t* a, const uint32_t* b) {
    asm volatile(
        "mma.sync.aligned.m16n8k8.row.col.f32.tf32.tf32.f32 "
        "{%0,%1,%2,%3}, {%4,%5,%6,%7}, {%8,%9}, {%0,%1,%2,%3};"
        : "+f"(d[0]), "+f"(d[1]), "+f"(d[2]), "+f"(d[3])
        : "r"(a[0]), "r"(a[1]), "r"(a[2]), "r"(a[3]), "r"(b[0]), "r"(b[1]));
}

// Shared-memory tile geometry (padded, conflict-free) — identical to the 677us build
#define ASTR 36     // A row stride (floats): bank = (4g+8ks+tq)%32 distinct
#define BSTR 136    // B row stride (floats): bank = (8tq+g)%32 distinct
#define A_STG (128*ASTR)            // floats per A stage
#define B_STG (32*BSTR)             // floats per B stage
#define SM_AS 512                                   // after s_tok[128]
#define SM_BS (SM_AS + 2*A_STG*4)                   // 512 + 36864 = 37376
#define GEMM_SMEM (SM_BS + 2*B_STG*4)               // + 34816 = 72192 (2 CTA/SM)

// ==================== reset counters (graph replays) ====================
__global__ void zero_kernel() {
    int i = threadIdx.x;
    if (i < EDIM) { g_freq[i] = 0; g_cursor[i] = 0; g_psum[i] = 0.f; }
    if (i == 0) g_lsesq = 0.f;
}

// ==================== router ====================
__global__ void router_kernel(const float* __restrict__ x,
                              const float* __restrict__ wr) {
    __shared__ float s_p[EDIM];
    __shared__ float s_lsesq;
    int tid = threadIdx.x;
    if (tid < EDIM) s_p[tid] = 0.f;
    if (tid == 0) s_lsesq = 0.f;
    __syncthreads();

    int t = blockIdx.x * 8 + (tid >> 5);
    int lane = tid & 31;

    float acc[8] = {0.f,0.f,0.f,0.f,0.f,0.f,0.f,0.f};
    const float* xp = x + (size_t)t * HDIM;
    for (int h = lane; h < HDIM; h += 32) {
        float xv = xp[h];
        float4 w0 = *(const float4*)(wr + h * 8);
        float4 w1 = *(const float4*)(wr + h * 8 + 4);
        acc[0] += xv * w0.x; acc[1] += xv * w0.y;
        acc[2] += xv * w0.z; acc[3] += xv * w0.w;
        acc[4] += xv * w1.x; acc[5] += xv * w1.y;
        acc[6] += xv * w1.z; acc[7] += xv * w1.w;
    }
#pragma unroll
    for (int e = 0; e < 8; e++)
#pragma unroll
        for (int o = 16; o > 0; o >>= 1)
            acc[e] += __shfl_down_sync(0xffffffffu, acc[e], o);

    if (lane == 0) {
        float m = acc[0];
#pragma unroll
        for (int e = 1; e < 8; e++) m = fmaxf(m, acc[e]);
        float ex[8], sum = 0.f;
#pragma unroll
        for (int e = 0; e < 8; e++) { ex[e] = expf(acc[e] - m); sum += ex[e]; }
        float inv = 1.f / sum;
        float lse = m + logf(sum);

        int i0 = 0;
#pragma unroll
        for (int e = 1; e < 8; e++) if (acc[e] > acc[i0]) i0 = e;
        int i1 = (i0 == 0) ? 1 : 0;
#pragma unroll
        for (int e = 0; e < 8; e++) if (e != i0 && acc[e] > acc[i1]) i1 = e;

        float d = expf(acc[i1] - acc[i0]);
        float g0 = 1.f / (1.f + d);
        float g1 = d / (1.f + d);

        g_eid[2 * t]     = i0;  g_eid[2 * t + 1]  = i1;
        g_gate[2 * t]    = g0;  g_gate[2 * t + 1] = g1;
        atomicAdd(&g_freq[i0], 1);
        atomicAdd(&g_freq[i1], 1);
#pragma unroll
        for (int e = 0; e < 8; e++) atomicAdd(&s_p[e], ex[e] * inv);
        atomicAdd(&s_lsesq, lse * lse);
    }
    __syncthreads();
    if (tid < EDIM) atomicAdd(&g_psum[tid], s_p[tid]);
    if (tid == 0)   atomicAdd(&g_lsesq, s_lsesq);
}

__global__ void scan_kernel() {
    if (threadIdx.x == 0) {
        int s = 0;
        for (int e = 0; e < EDIM; e++) { g_offsets[e] = s; s += g_freq[e]; }
        g_offsets[EDIM] = s;
    }
}

__global__ void scatter_kernel() {
    int r = blockIdx.x * blockDim.x + threadIdx.x;
    if (r < NROWS) {
        int e = g_eid[r];
        int pos = atomicAdd(&g_cursor[e], 1);
        g_list[g_offsets[e] + pos] = r;
    }
}

// ==================== tile loaders (256 threads) ====================
// A: 128 gathered rows x 32 K-floats. B: 32 K-rows x 128 cols.
__device__ __forceinline__ void g1_load(const float* __restrict__ x,
                                        const float* __restrict__ w1,
                                        const int* s_tok,
                                        uint32_t as_u, uint32_t bs_u,
                                        int tid, int n0, int c, int st) {
    const int k0 = c * 32;
#pragma unroll
    for (int i = 0; i < 4; i++) {                 // 1024 16B-chunks / 256 thr
        int idx = tid + i * 256;
        int row = idx >> 3, seg = idx & 7;
        const float* src = x + (size_t)s_tok[row] * HDIM + k0 + seg * 4;
        cp16(as_u + (uint32_t)((st * A_STG + row * ASTR + seg * 4) * 4), src);
    }
#pragma unroll
    for (int i = 0; i < 4; i++) {                 // 1024 chunks / 256 thr
        int idx = tid + i * 256;
        int kr = idx >> 5, j = (idx & 31) * 4;
        int half = (j >> 5) & 1, blk = j >> 6, cloc = j & 31;
        int wcol = n0 + blk * 32 + cloc + (half ? FDIM : 0);
        const float* src = w1 + (size_t)(k0 + kr) * (2 * FDIM) + wcol;
        cp16(bs_u + (uint32_t)((st * B_STG + kr * BSTR + j) * 4), src);
    }
    CP_COMMIT();
}

__device__ __forceinline__ void g2_load(const float* __restrict__ w2,
                                        int off, int row0, int rlim,
                                        uint32_t as_u, uint32_t bs_u,
                                        int tid, int n1, int c, int st) {
    const int k0 = c * 32;
#pragma unroll
    for (int i = 0; i < 4; i++) {
        int idx = tid + i * 256;
        int row = idx >> 3, seg = idx & 7;
        int rr = (row < rlim) ? row : (rlim - 1);
        const float* src = g_glu + (size_t)(off + row0 + rr) * FDIM + k0 + seg * 4;
        cp16(as_u + (uint32_t)((st * A_STG + row * ASTR + seg * 4) * 4), src);
    }
#pragma unroll
    for (int i = 0; i < 4; i++) {
        int idx = tid + i * 256;
        int kr = idx >> 5, j = (idx & 31) * 4;
        const float* src = w2 + (size_t)(k0 + kr) * HDIM + n1 + j;
        cp16(bs_u + (uint32_t)((st * B_STG + kr * BSTR + j) * 4), src);
    }
    CP_COMMIT();
}

// compute one K-chunk: warp tile 32x64 (2 m-frags x 8 n-frags)
__device__ __forceinline__ void chunk_mma(const float* Ast, const float* Bst,
                                          int wm, int wn, int g, int tq,
                                          float acc[2][8][4]) {
#pragma unroll
    for (int ks = 0; ks < 4; ks++) {
        uint32_t af[2][4];
#pragma unroll
        for (int i = 0; i < 2; i++) {
            const float* ap = Ast + (wm * 32 + i * 16 + g) * ASTR + ks * 8 + tq;
            af[i][0] = f2tf32(ap[0]);
            af[i][1] = f2tf32(ap[8 * ASTR]);
            af[i][2] = f2tf32(ap[4]);
            af[i][3] = f2tf32(ap[8 * ASTR + 4]);
        }
        uint32_t bf[8][2];
#pragma unroll
        for (int f = 0; f < 8; f++) {
            const float* bp = Bst + (ks * 8 + tq) * BSTR + wn * 64 + f * 8 + g;
            bf[f][0] = f2tf32(bp[0]);
            bf[f][1] = f2tf32(bp[4 * BSTR]);
        }
#pragma unroll
        for (int i = 0; i < 2; i++)
#pragma unroll
            for (int f = 0; f < 8; f++)
                mma_tf32(acc[i][f], af[i], bf[f]);
    }
}

// ==================== GEMM1: x[tok] @ w_in[e], fused GLU ====================
// CTA tile 128 rows x (64 a-cols + 64 gv-cols). 8 warps of 32x64 (wm 0..3, wn 0..1).
__global__ void __launch_bounds__(256, 2) gemm1_mma(const float* __restrict__ x,
                                                    const float* __restrict__ w_in) {
    const int e = blockIdx.z;
    const int cnt = g_freq[e];
    const int row0 = blockIdx.y * 128;
    if (row0 >= cnt) return;
    const int off = g_offsets[e];
    const int n0 = blockIdx.x * 64;

    extern __shared__ char smem[];
    int* s_tok = (int*)smem;
    float* As = (float*)(smem + SM_AS);
    float* Bs = (float*)(smem + SM_BS);
    const uint32_t as_u = smem_u32(As), bs_u = smem_u32(Bs);

    const int tid = threadIdx.x;
    if (tid < 128) {
        int r = row0 + tid;
        s_tok[tid] = g_list[off + ((r < cnt) ? r : (cnt - 1))] >> 1;
    }
    __syncthreads();

    const float* w1 = w_in + (size_t)e * HDIM * (2 * FDIM);

    const int lane = tid & 31, wid = tid >> 5;
    const int wm = wid & 3, wn = wid >> 2;
    const int g = lane >> 2, tq = lane & 3;

    float acc[2][8][4];
#pragma unroll
    for (int i = 0; i < 2; i++)
#pragma unroll
        for (int f = 0; f < 8; f++)
#pragma unroll
            for (int q = 0; q < 4; q++) acc[i][f][q] = 0.f;

    const int NCH = HDIM / 32;  // 32
    g1_load(x, w1, s_tok, as_u, bs_u, tid, n0, 0, 0);
    g1_load(x, w1, s_tok, as_u, bs_u, tid, n0, 1, 1);
    CP_WAIT1();
    __syncthreads();

    for (int c = 0; c < NCH; c++) {
        const int st = c & 1;
        chunk_mma(As + st * A_STG, Bs + st * B_STG, wm, wn, g, tq, acc);
        __syncthreads();
        if (c + 2 < NCH) g1_load(x, w1, s_tok, as_u, bs_u, tid, n0, c + 2, st);
        if (c + 1 < NCH) {
            if (c + 2 < NCH) CP_WAIT1(); else CP_WAIT0();
            __syncthreads();
        }
    }

    // epilogue: GLU (warp wn pairs a-frag f with gv-frag f+4 over cols n0+wn*32)
#pragma unroll
    for (int i = 0; i < 2; i++) {
        const int rbase = wm * 32 + i * 16 + g;
#pragma unroll
        for (int hr = 0; hr < 2; hr++) {
            const int r = rbase + hr * 8;
            if (row0 + r < cnt) {
                float* dst = g_glu + (size_t)(off + row0 + r) * FDIM + n0 + wn * 32;
#pragma unroll
                for (int f = 0; f < 4; f++) {
                    float a0 = acc[i][f][hr * 2], a1 = acc[i][f][hr * 2 + 1];
                    float v0 = acc[i][f + 4][hr * 2], v1 = acc[i][f + 4][hr * 2 + 1];
                    float2 o;
                    o.x = (a0 / (1.f + __expf(-a0))) * v0;
                    o.y = (a1 / (1.f + __expf(-a1))) * v1;
                    *(float2*)(dst + f * 8 + 2 * tq) = o;
                }
            }
        }
    }
}

// ==================== GEMM2: glu @ w_out[e], fused gate-scale scatter ====================
__global__ void __launch_bounds__(256, 2) gemm2_mma(const float* __restrict__ w_out) {
    const int e = blockIdx.z;
    const int cnt = g_freq[e];
    const int row0 = blockIdx.y * 128;
    if (row0 >= cnt) return;
    const int off = g_offsets[e];
    const int n1 = blockIdx.x * 128;
    const int rlim = cnt - row0;

    extern __shared__ char smem[];
    int* s_dst = (int*)smem;
    float* As = (float*)(smem + SM_AS);
    float* Bs = (float*)(smem + SM_BS);
    const uint32_t as_u = smem_u32(As), bs_u = smem_u32(Bs);

    const int tid = threadIdx.x;
    if (tid < 128) {
        int r = row0 + tid;
        s_dst[tid] = g_list[off + ((r < cnt) ? r : (cnt - 1))];
    }
    __syncthreads();

    const float* w2 = w_out + (size_t)e * FDIM * HDIM;

    const int lane = tid & 31, wid = tid >> 5;
    const int wm = wid & 3, wn = wid >> 2;
    const int g = lane >> 2, tq = lane & 3;

    float acc[2][8][4];
#pragma unroll
    for (int i = 0; i < 2; i++)
#pragma unroll
        for (int f = 0; f < 8; f++)
#pragma unroll
            for (int q = 0; q < 4; q++) acc[i][f][q] = 0.f;

    const int NCH = FDIM / 32;  // 64
    g2_load(w2, off, row0, rlim, as_u, bs_u, tid, n1, 0, 0);
    g2_load(w2, off, row0, rlim, as_u, bs_u, tid, n1, 1, 1);
    CP_WAIT1();
    __syncthreads();

    for (int c = 0; c < NCH; c++) {
        const int st = c & 1;
        chunk_mma(As + st * A_STG, Bs + st * B_STG, wm, wn, g, tq, acc);
        __syncthreads();
        if (c + 2 < NCH) g2_load(w2, off, row0, rlim, as_u, bs_u, tid, n1, c + 2, st);
        if (c + 1 < NCH) {
            if (c + 2 < NCH) CP_WAIT1(); else CP_WAIT0();
            __syncthreads();
        }
    }

    // epilogue: scale by gate, scatter rows to g_pairs[dst]
#pragma unroll
    for (int i = 0; i < 2; i++) {
        const int rbase = wm * 32 + i * 16 + g;
#pragma unroll
        for (int hr = 0; hr < 2; hr++) {
            const int r = rbase + hr * 8;
            if (r < rlim) {
                const int dst = s_dst[r];
                const float gt = g_gate[dst];
                float* op = g_pairs + (size_t)dst * HDIM + n1 + wn * 64;
#pragma unroll
                for (int f = 0; f < 8; f++) {
                    float2 o;
                    o.x = acc[i][f][hr * 2] * gt;
                    o.y = acc[i][f][hr * 2 + 1] * gt;
                    *(float2*)(op + f * 8 + 2 * tq) = o;
                }
            }
        }
    }
}

// ==================== combine + loss ====================
__global__ void combine_kernel(float* __restrict__ out, const float* __restrict__ bias) {
    int i = blockIdx.x * blockDim.x + threadIdx.x;
    if (i < TDIM * HDIM / 4) {
        int t = i >> 8;
        int c4 = i & 255;
        const float4* p4 = (const float4*)g_pairs;
        float4 a = p4[(size_t)(2 * t) * 256 + c4];
        float4 b = p4[(size_t)(2 * t) * 256 + 256 + c4];
        float4 bs = ((const float4*)bias)[c4];
        float4 o;
        o.x = a.x + b.x + bs.x; o.y = a.y + b.y + bs.y;
        o.z = a.z + b.z + bs.z; o.w = a.w + b.w + bs.w;
        ((float4*)out)[i] = o;
    }
}

__global__ void loss_kernel(float* __restrict__ out, int out_size) {
    if (threadIdx.x == 0 && blockIdx.x == 0) {
        float s = 0.f;
        for (int e = 0; e < EDIM; e++) s += g_psum[e] * (float)g_freq[e];
        float loss = (float)EDIM * s / ((float)TDIM * (float)(TDIM * KSEL))
                   + 0.1f * g_lsesq / (float)TDIM;
        if (out_size > TDIM * HDIM) out[TDIM * HDIM] = loss;
    }
}

// ==================== launch ====================
extern "C" void kernel_launch(void* const* d_in, const int* in_sizes, int n_in,
                              void* d_out, int out_size) {
    const float* x        = (const float*)d_in[0];
    const float* w_router = (const float*)d_in[1];
    const float* w_in     = (const float*)d_in[2];
    const float* w_out    = (const float*)d_in[3];
    const float* bias     = (const float*)d_in[4];
    float* out = (float*)d_out;

    cudaFuncSetAttribute(gemm1_mma, cudaFuncAttributeMaxDynamicSharedMemorySize, GEMM_SMEM);
    cudaFuncSetAttribute(gemm2_mma, cudaFuncAttributeMaxDynamicSharedMemorySize, GEMM_SMEM);

    zero_kernel<<<1, 32>>>();
    router_kernel<<<TDIM / 8, 256>>>(x, w_router);
    scan_kernel<<<1, 32>>>();
    scatter_kernel<<<NROWS / 256, 256>>>();

    gemm1_mma<<<dim3(FDIM / 64, TDIM / 128, EDIM), 256, GEMM_SMEM>>>(x, w_in);
    gemm2_mma<<<dim3(HDIM / 128, TDIM / 128, EDIM), 256, GEMM_SMEM>>>(w_out);

    combine_kernel<<<(TDIM * HDIM / 4 + 255) / 256, 256>>>(out, bias);
    loss_kernel<<<1, 32>>>(out, out_size);
}

// round 14
// speedup vs baseline: 1.4601x; 1.4601x over previous
#include <cuda_runtime.h>
#include <cuda_fp16.h>
#include <math.h>
#include <stdint.h>

// Problem constants
#define TDIM 4096          // B*S tokens
#define HDIM 1024          // hidden
#define EDIM 8             // experts
#define FDIM 2048          // ffn
#define KSEL 2             // top-k
#define NROWS (TDIM*KSEL)  // 8192 dispatch rows

// ==================== device scratch (allocation-free) ====================
__device__ __half g_xh[(size_t)TDIM * HDIM];              // x as fp16 [T][H]
__device__ __half g_w1h[(size_t)EDIM * 2 * FDIM * HDIM];  // w_in  fp16 transposed [E][2F][H]
__device__ __half g_w2h[(size_t)EDIM * HDIM * FDIM];      // w_out fp16 transposed [E][H][F]
__device__ __half g_glu[(size_t)NROWS * FDIM];            // GLU acts fp16 (list order)
__device__ float  g_pairs[(size_t)NROWS * HDIM];          // expert outputs per (token,slot)
__device__ int   g_eid[NROWS];
__device__ float g_gate[NROWS];
__device__ int   g_list[NROWS];
__device__ int   g_freq[EDIM];
__device__ int   g_cursor[EDIM];
__device__ int   g_offsets[EDIM + 1];
__device__ float g_psum[EDIM];
__device__ float g_lsesq;

// ==================== PTX helpers (sm_80-baseline features only) ====================
__device__ __forceinline__ uint32_t smem_u32(const void* p) {
    uint32_t a;
    asm("{ .reg .u64 t; cvta.to.shared.u64 t, %1; cvt.u32.u64 %0, t; }" : "=r"(a) : "l"(p));
    return a;
}
__device__ __forceinline__ void cp16(uint32_t dst, const void* src) {
    asm volatile("cp.async.cg.shared.global [%0], [%1], 16;" :: "r"(dst), "l"(src));
}
#define CP_COMMIT() asm volatile("cp.async.commit_group;" ::: "memory")
#define CP_WAIT1()  asm volatile("cp.async.wait_group 1;" ::: "memory")
#define CP_WAIT0()  asm volatile("cp.async.wait_group 0;" ::: "memory")

// fp16 MMA: D(16x8,f32) += A(16x16,f16) * B(16x8,f16)  [row.col]
__device__ __forceinline__ void mma_f16(float* d, const uint32_t* a, const uint32_t* b) {
    asm volatile(
        "mma.sync.aligned.m16n8k16.row.col.f32.f16.f16.f32 "
        "{%0,%1,%2,%3}, {%4,%5,%6,%7}, {%8,%9}, {%0,%1,%2,%3};"
        : "+f"(d[0]), "+f"(d[1]), "+f"(d[2]), "+f"(d[3])
        : "r"(a[0]), "r"(a[1]), "r"(a[2]), "r"(a[3]), "r"(b[0]), "r"(b[1]));
}

// ---- Shared-memory tile geometry (fp16, padded rows) ----
// A tile: 128 rows x 32 fp16 (64B data), padded to 80B/row.
//   Fragment bank = (g*20 + tq + const)%32 -> 32 distinct, conflict-free.
// B tile: 128 n-rows x 32 fp16 (col-major for mma), padded to 80B/row. Same proof.
#define ROWB 80                              // padded row bytes
#define A_STG_B (128*ROWB)                   // 10240 B per stage
#define B_STG_B (128*ROWB)                   // 10240 B per stage
#define SM_AS 512                            // after s_tok[128]
#define SM_BS (SM_AS + 2*A_STG_B)            // 512 + 20480 = 20992
#define GEMM_SMEM (SM_BS + 2*B_STG_B)        // + 20480 = 41472 (2+ CTA/SM)

// ==================== reset counters (graph replays) ====================
__global__ void zero_kernel() {
    int i = threadIdx.x;
    if (i < EDIM) { g_freq[i] = 0; g_cursor[i] = 0; g_psum[i] = 0.f; }
    if (i == 0) g_lsesq = 0.f;
}

// ==================== fp16 conversions ====================
__global__ void convx_kernel(const float4* __restrict__ src, uint2* __restrict__ dst, int n4) {
    int i = blockIdx.x * 256 + threadIdx.x;
    if (i < n4) {
        float4 v = src[i];
        __half2 h01 = __floats2half2_rn(v.x, v.y);
        __half2 h23 = __floats2half2_rn(v.z, v.w);
        uint2 o;
        o.x = *(uint32_t*)&h01;
        o.y = *(uint32_t*)&h23;
        dst[i] = o;
    }
}

// w_in (E,H,2F) fp32 -> g_w1h (E,2F,H) fp16
__global__ void t_w1_kernel(const float* __restrict__ w) {
    __shared__ float tile[32][33];
    int e = blockIdx.z;
    int n0 = blockIdx.x * 32, h0 = blockIdx.y * 32;
    int tx = threadIdx.x, ty = threadIdx.y;
    const float* src = w + (size_t)e * HDIM * (2 * FDIM);
#pragma unroll
    for (int i = 0; i < 4; i++)
        tile[ty + i * 8][tx] = src[(size_t)(h0 + ty + i * 8) * (2 * FDIM) + n0 + tx];
    __syncthreads();
    __half* dst = g_w1h + (size_t)e * (2 * FDIM) * HDIM;
#pragma unroll
    for (int i = 0; i < 4; i++)
        dst[(size_t)(n0 + ty + i * 8) * HDIM + h0 + tx] = __float2half_rn(tile[tx][ty + i * 8]);
}

// w_out (E,F,H) fp32 -> g_w2h (E,H,F) fp16
__global__ void t_w2_kernel(const float* __restrict__ w) {
    __shared__ float tile[32][33];
    int e = blockIdx.z;
    int h0 = blockIdx.x * 32, f0 = blockIdx.y * 32;
    int tx = threadIdx.x, ty = threadIdx.y;
    const float* src = w + (size_t)e * FDIM * HDIM;
#pragma unroll
    for (int i = 0; i < 4; i++)
        tile[ty + i * 8][tx] = src[(size_t)(f0 + ty + i * 8) * HDIM + h0 + tx];
    __syncthreads();
    __half* dst = g_w2h + (size_t)e * HDIM * FDIM;
#pragma unroll
    for (int i = 0; i < 4; i++)
        dst[(size_t)(h0 + ty + i * 8) * FDIM + f0 + tx] = __float2half_rn(tile[tx][ty + i * 8]);
}

// ==================== router ====================
__global__ void router_kernel(const float* __restrict__ x,
                              const float* __restrict__ wr) {
    __shared__ float s_p[EDIM];
    __shared__ float s_lsesq;
    int tid = threadIdx.x;
    if (tid < EDIM) s_p[tid] = 0.f;
    if (tid == 0) s_lsesq = 0.f;
    __syncthreads();

    int t = blockIdx.x * 8 + (tid >> 5);
    int lane = tid & 31;

    float acc[8] = {0.f,0.f,0.f,0.f,0.f,0.f,0.f,0.f};
    const float* xp = x + (size_t)t * HDIM;
    for (int h = lane; h < HDIM; h += 32) {
        float xv = xp[h];
        float4 w0 = *(const float4*)(wr + h * 8);
        float4 w1 = *(const float4*)(wr + h * 8 + 4);
        acc[0] += xv * w0.x; acc[1] += xv * w0.y;
        acc[2] += xv * w0.z; acc[3] += xv * w0.w;
        acc[4] += xv * w1.x; acc[5] += xv * w1.y;
        acc[6] += xv * w1.z; acc[7] += xv * w1.w;
    }
#pragma unroll
    for (int e = 0; e < 8; e++)
#pragma unroll
        for (int o = 16; o > 0; o >>= 1)
            acc[e] += __shfl_down_sync(0xffffffffu, acc[e], o);

    if (lane == 0) {
        float m = acc[0];
#pragma unroll
        for (int e = 1; e < 8; e++) m = fmaxf(m, acc[e]);
        float ex[8], sum = 0.f;
#pragma unroll
        for (int e = 0; e < 8; e++) { ex[e] = expf(acc[e] - m); sum += ex[e]; }
        float inv = 1.f / sum;
        float lse = m + logf(sum);

        int i0 = 0;
#pragma unroll
        for (int e = 1; e < 8; e++) if (acc[e] > acc[i0]) i0 = e;
        int i1 = (i0 == 0) ? 1 : 0;
#pragma unroll
        for (int e = 0; e < 8; e++) if (e != i0 && acc[e] > acc[i1]) i1 = e;

        float d = expf(acc[i1] - acc[i0]);
        float g0 = 1.f / (1.f + d);
        float g1 = d / (1.f + d);

        g_eid[2 * t]     = i0;  g_eid[2 * t + 1]  = i1;
        g_gate[2 * t]    = g0;  g_gate[2 * t + 1] = g1;
        atomicAdd(&g_freq[i0], 1);
        atomicAdd(&g_freq[i1], 1);
#pragma unroll
        for (int e = 0; e < 8; e++) atomicAdd(&s_p[e], ex[e] * inv);
        atomicAdd(&s_lsesq, lse * lse);
    }
    __syncthreads();
    if (tid < EDIM) atomicAdd(&g_psum[tid], s_p[tid]);
    if (tid == 0)   atomicAdd(&g_lsesq, s_lsesq);
}

__global__ void scan_kernel() {
    if (threadIdx.x == 0) {
        int s = 0;
        for (int e = 0; e < EDIM; e++) { g_offsets[e] = s; s += g_freq[e]; }
        g_offsets[EDIM] = s;
    }
}

__global__ void scatter_kernel() {
    int r = blockIdx.x * blockDim.x + threadIdx.x;
    if (r < NROWS) {
        int e = g_eid[r];
        int pos = atomicAdd(&g_cursor[e], 1);
        g_list[g_offsets[e] + pos] = r;
    }
}

// ==================== tile loaders (128 threads, fp16) ====================
// Per chunk: A = 128 rows x 32 fp16 (512 cp16), B = 128 n-rows x 32 fp16 (512 cp16).
__device__ __forceinline__ void g1_load(const __half* __restrict__ w1,
                                        const int* s_tok,
                                        uint32_t as_u, uint32_t bs_u,
                                        int tid, int n0, int c, int st) {
    const int k0 = c * 32;
#pragma unroll
    for (int i = 0; i < 4; i++) {
        int idx = tid + i * 128;
        int row = idx >> 2, seg = idx & 3;
        const __half* src = g_xh + (size_t)s_tok[row] * HDIM + k0 + seg * 8;
        cp16(as_u + (uint32_t)(st * A_STG_B + row * ROWB + seg * 16), src);
    }
#pragma unroll
    for (int i = 0; i < 4; i++) {
        int idx = tid + i * 128;
        int j = idx >> 2, seg = idx & 3;
        int blk = j >> 6, half = (j >> 5) & 1, cloc = j & 31;
        int n = (half ? FDIM : 0) + n0 + blk * 32 + cloc;
        const __half* src = w1 + (size_t)n * HDIM + k0 + seg * 8;
        cp16(bs_u + (uint32_t)(st * B_STG_B + j * ROWB + seg * 16), src);
    }
    CP_COMMIT();
}

__device__ __forceinline__ void g2_load(const __half* __restrict__ w2,
                                        int off, int row0, int rlim,
                                        uint32_t as_u, uint32_t bs_u,
                                        int tid, int n1, int c, int st) {
    const int k0 = c * 32;
#pragma unroll
    for (int i = 0; i < 4; i++) {
        int idx = tid + i * 128;
        int row = idx >> 2, seg = idx & 3;
        int rr = (row < rlim) ? row : (rlim - 1);
        const __half* src = g_glu + (size_t)(off + row0 + rr) * FDIM + k0 + seg * 8;
        cp16(as_u + (uint32_t)(st * A_STG_B + row * ROWB + seg * 16), src);
    }
#pragma unroll
    for (int i = 0; i < 4; i++) {
        int idx = tid + i * 128;
        int j = idx >> 2, seg = idx & 3;
        const __half* src = w2 + (size_t)(n1 + j) * FDIM + k0 + seg * 8;
        cp16(bs_u + (uint32_t)(st * B_STG_B + j * ROWB + seg * 16), src);
    }
    CP_COMMIT();
}

// compute one K=32 chunk: 2 x m16n8k16 steps; warp tile 64x64 (4 m-frags x 8 n-frags)
__device__ __forceinline__ void chunk_mma(const char* Ast, const char* Bst,
                                          int wm, int wn, int g, int tq,
                                          float acc[4][8][4]) {
#pragma unroll
    for (int ks = 0; ks < 2; ks++) {
        const int kb = ks * 32 + 4 * tq;   // byte offset of (k=2tq) within ks-step
        uint32_t af[4][4];
#pragma unroll
        for (int i = 0; i < 4; i++) {
            const char* ar0 = Ast + (wm * 64 + i * 16 + g) * ROWB;
            const char* ar1 = ar0 + 8 * ROWB;
            af[i][0] = *(const uint32_t*)(ar0 + kb);
            af[i][1] = *(const uint32_t*)(ar1 + kb);
            af[i][2] = *(const uint32_t*)(ar0 + kb + 16);
            af[i][3] = *(const uint32_t*)(ar1 + kb + 16);
        }
        uint32_t bf[8][2];
#pragma unroll
        for (int f = 0; f < 8; f++) {
            const char* br = Bst + (wn * 64 + f * 8 + g) * ROWB;
            bf[f][0] = *(const uint32_t*)(br + kb);
            bf[f][1] = *(const uint32_t*)(br + kb + 16);
        }
#pragma unroll
        for (int i = 0; i < 4; i++)
#pragma unroll
            for (int f = 0; f < 8; f++)
                mma_f16(acc[i][f], af[i], bf[f]);
    }
}

// ==================== GEMM1: x[tok] @ w_in[e], fused GLU ====================
// CTA tile 128 rows x (64 a-cols + 64 gv-cols). 4 warps of 64x64.
__global__ void __launch_bounds__(128) gemm1_mma(const __half* __restrict__ w1e) {
    const int e = blockIdx.z;
    const int cnt = g_freq[e];
    const int row0 = blockIdx.y * 128;
    if (row0 >= cnt) return;
    const int off = g_offsets[e];
    const int n0 = blockIdx.x * 64;

    extern __shared__ char smem[];
    int* s_tok = (int*)smem;
    char* As = smem + SM_AS;
    char* Bs = smem + SM_BS;
    const uint32_t as_u = smem_u32(As), bs_u = smem_u32(Bs);

    const int tid = threadIdx.x;
    {
        int r = row0 + tid;
        s_tok[tid] = g_list[off + ((r < cnt) ? r : (cnt - 1))] >> 1;
    }
    __syncthreads();

    const __half* w1 = w1e + (size_t)e * (2 * FDIM) * HDIM;

    const int lane = tid & 31, wid = tid >> 5;
    const int wm = wid & 1, wn = wid >> 1;
    const int g = lane >> 2, tq = lane & 3;

    float acc[4][8][4];
#pragma unroll
    for (int i = 0; i < 4; i++)
#pragma unroll
        for (int f = 0; f < 8; f++)
#pragma unroll
            for (int q = 0; q < 4; q++) acc[i][f][q] = 0.f;

    const int NCH = HDIM / 32;  // 32
    g1_load(w1, s_tok, as_u, bs_u, tid, n0, 0, 0);
    g1_load(w1, s_tok, as_u, bs_u, tid, n0, 1, 1);
    CP_WAIT1();
    __syncthreads();

    for (int c = 0; c < NCH; c++) {
        const int st = c & 1;
        chunk_mma(As + st * A_STG_B, Bs + st * B_STG_B, wm, wn, g, tq, acc);
        __syncthreads();
        if (c + 2 < NCH) g1_load(w1, s_tok, as_u, bs_u, tid, n0, c + 2, st);
        if (c + 1 < NCH) {
            if (c + 2 < NCH) CP_WAIT1(); else CP_WAIT0();
            __syncthreads();
        }
    }

    // epilogue: GLU -> fp16 g_glu (warp wn pairs a-frag f with gv-frag f+4)
#pragma unroll
    for (int i = 0; i < 4; i++) {
        const int rbase = wm * 64 + i * 16 + g;
#pragma unroll
        for (int hr = 0; hr < 2; hr++) {
            const int r = rbase + hr * 8;
            if (row0 + r < cnt) {
                __half2* dst = (__half2*)(g_glu + (size_t)(off + row0 + r) * FDIM + n0 + wn * 32);
#pragma unroll
                for (int f = 0; f < 4; f++) {
                    float a0 = acc[i][f][hr * 2], a1 = acc[i][f][hr * 2 + 1];
                    float v0 = acc[i][f + 4][hr * 2], v1 = acc[i][f + 4][hr * 2 + 1];
                    float o0 = (a0 / (1.f + __expf(-a0))) * v0;
                    float o1 = (a1 / (1.f + __expf(-a1))) * v1;
                    dst[f * 4 + tq] = __floats2half2_rn(o0, o1);
                }
            }
        }
    }
}

// ==================== GEMM2: glu @ w_out[e], fused gate-scale scatter ====================
__global__ void __launch_bounds__(128) gemm2_mma(const __half* __restrict__ w2e) {
    const int e = blockIdx.z;
    const int cnt = g_freq[e];
    const int row0 = blockIdx.y * 128;
    if (row0 >= cnt) return;
    const int off = g_offsets[e];
    const int n1 = blockIdx.x * 128;
    const int rlim = cnt - row0;

    extern __shared__ char smem[];
    int* s_dst = (int*)smem;
    char* As = smem + SM_AS;
    char* Bs = smem + SM_BS;
    const uint32_t as_u = smem_u32(As), bs_u = smem_u32(Bs);

    const int tid = threadIdx.x;
    {
        int r = row0 + tid;
        s_dst[tid] = g_list[off + ((r < cnt) ? r : (cnt - 1))];
    }
    __syncthreads();

    const __half* w2 = w2e + (size_t)e * HDIM * FDIM;

    const int lane = tid & 31, wid = tid >> 5;
    const int wm = wid & 1, wn = wid >> 1;
    const int g = lane >> 2, tq = lane & 3;

    float acc[4][8][4];
#pragma unroll
    for (int i = 0; i < 4; i++)
#pragma unroll
        for (int f = 0; f < 8; f++)
#pragma unroll
            for (int q = 0; q < 4; q++) acc[i][f][q] = 0.f;

    const int NCH = FDIM / 32;  // 64
    g2_load(w2, off, row0, rlim, as_u, bs_u, tid, n1, 0, 0);
    g2_load(w2, off, row0, rlim, as_u, bs_u, tid, n1, 1, 1);
    CP_WAIT1();
    __syncthreads();

    for (int c = 0; c < NCH; c++) {
        const int st = c & 1;
        chunk_mma(As + st * A_STG_B, Bs + st * B_STG_B, wm, wn, g, tq, acc);
        __syncthreads();
        if (c + 2 < NCH) g2_load(w2, off, row0, rlim, as_u, bs_u, tid, n1, c + 2, st);
        if (c + 1 < NCH) {
            if (c + 2 < NCH) CP_WAIT1(); else CP_WAIT0();
            __syncthreads();
        }
    }

    // epilogue: scale by gate, scatter rows to g_pairs[dst]
#pragma unroll
    for (int i = 0; i < 4; i++) {
        const int rbase = wm * 64 + i * 16 + g;
#pragma unroll
        for (int hr = 0; hr < 2; hr++) {
            const int r = rbase + hr * 8;
            if (r < rlim) {
                const int dst = s_dst[r];
                const float gt = g_gate[dst];
                float* op = g_pairs + (size_t)dst * HDIM + n1 + wn * 64;
#pragma unroll
                for (int f = 0; f < 8; f++) {
                    float2 o;
                    o.x = acc[i][f][hr * 2] * gt;
                    o.y = acc[i][f][hr * 2 + 1] * gt;
                    *(float2*)(op + f * 8 + 2 * tq) = o;
                }
            }
        }
    }
}

// ==================== combine + loss ====================
__global__ void combine_kernel(float* __restrict__ out, const float* __restrict__ bias) {
    int i = blockIdx.x * blockDim.x + threadIdx.x;
    if (i < TDIM * HDIM / 4) {
        int t = i >> 8;
        int c4 = i & 255;
        const float4* p4 = (const float4*)g_pairs;
        float4 a = p4[(size_t)(2 * t) * 256 + c4];
        float4 b = p4[(size_t)(2 * t) * 256 + 256 + c4];
        float4 bs = ((const float4*)bias)[c4];
        float4 o;
        o.x = a.x + b.x + bs.x; o.y = a.y + b.y + bs.y;
        o.z = a.z + b.z + bs.z; o.w = a.w + b.w + bs.w;
        ((float4*)out)[i] = o;
    }
}

__global__ void loss_kernel(float* __restrict__ out, int out_size) {
    if (threadIdx.x == 0 && blockIdx.x == 0) {
        float s = 0.f;
        for (int e = 0; e < EDIM; e++) s += g_psum[e] * (float)g_freq[e];
        float loss = (float)EDIM * s / ((float)TDIM * (float)(TDIM * KSEL))
                   + 0.1f * g_lsesq / (float)TDIM;
        if (out_size > TDIM * HDIM) out[TDIM * HDIM] = loss;
    }
}

// ==================== launch ====================
extern "C" void kernel_launch(void* const* d_in, const int* in_sizes, int n_in,
                              void* d_out, int out_size) {
    const float* x        = (const float*)d_in[0];
    const float* w_router = (const float*)d_in[1];
    const float* w_in     = (const float*)d_in[2];
    const float* w_out    = (const float*)d_in[3];
    const float* bias     = (const float*)d_in[4];
    float* out = (float*)d_out;

    cudaFuncSetAttribute(gemm1_mma, cudaFuncAttributeMaxDynamicSharedMemorySize, GEMM_SMEM);
    cudaFuncSetAttribute(gemm2_mma, cudaFuncAttributeMaxDynamicSharedMemorySize, GEMM_SMEM);

    // resolve device-scratch base addresses
    __half *xh_p, *w1h_p, *w2h_p;
    cudaGetSymbolAddress((void**)&xh_p, g_xh);
    cudaGetSymbolAddress((void**)&w1h_p, g_w1h);
    cudaGetSymbolAddress((void**)&w2h_p, g_w2h);

    zero_kernel<<<1, 32>>>();

    // fp16 conversions (x straight; weights transposed to n-major for col-major B)
    {
        int n4x = TDIM * HDIM / 4;
        convx_kernel<<<(n4x + 255) / 256, 256>>>((const float4*)x, (uint2*)xh_p, n4x);
        t_w1_kernel<<<dim3(2 * FDIM / 32, HDIM / 32, EDIM), dim3(32, 8)>>>(w_in);
        t_w2_kernel<<<dim3(HDIM / 32, FDIM / 32, EDIM), dim3(32, 8)>>>(w_out);
    }

    router_kernel<<<TDIM / 8, 256>>>(x, w_router);
    scan_kernel<<<1, 32>>>();
    scatter_kernel<<<NROWS / 256, 256>>>();

    gemm1_mma<<<dim3(FDIM / 64, TDIM / 128, EDIM), 128, GEMM_SMEM>>>(w1h_p);
    gemm2_mma<<<dim3(HDIM / 128, TDIM / 128, EDIM), 128, GEMM_SMEM>>>(w2h_p);

    combine_kernel<<<(TDIM * HDIM / 4 + 255) / 256, 256>>>(out, bias);
    loss_kernel<<<1, 32>>>(out, out_size);
}

// round 15
// speedup vs baseline: 1.5988x; 1.0950x over previous
#include <cuda_runtime.h>
#include <cuda_fp16.h>
#include <math.h>
#include <stdint.h>

// Problem constants
#define TDIM 4096          // B*S tokens
#define HDIM 1024          // hidden
#define EDIM 8             // experts
#define FDIM 2048          // ffn
#define KSEL 2             // top-k
#define NROWS (TDIM*KSEL)  // 8192 dispatch rows

// ==================== device scratch (allocation-free) ====================
__device__ __half g_xh[(size_t)TDIM * HDIM];              // x fp16 [T][H]
__device__ __half g_w1h[(size_t)EDIM * HDIM * 2 * FDIM];  // w_in  fp16 [E][H][2F] (original layout)
__device__ __half g_w2h[(size_t)EDIM * FDIM * HDIM];      // w_out fp16 [E][F][H]  (original layout)
__device__ __half g_glu[(size_t)NROWS * FDIM];            // GLU acts fp16 (list order)
__device__ float  g_pairs[(size_t)NROWS * HDIM];          // expert outputs per (token,slot)
__device__ int   g_eid[NROWS];
__device__ float g_gate[NROWS];
__device__ int   g_list[NROWS];
__device__ int   g_freq[EDIM];
__device__ int   g_cursor[EDIM];
__device__ int   g_offsets[EDIM + 1];
__device__ float g_psum[EDIM];
__device__ float g_lsesq;

// ==================== PTX helpers (sm_80-baseline features only) ====================
__device__ __forceinline__ uint32_t smem_u32(const void* p) {
    uint32_t a;
    asm("{ .reg .u64 t; cvta.to.shared.u64 t, %1; cvt.u32.u64 %0, t; }" : "=r"(a) : "l"(p));
    return a;
}
__device__ __forceinline__ void cp16(uint32_t dst, const void* src) {
    asm volatile("cp.async.cg.shared.global [%0], [%1], 16;" :: "r"(dst), "l"(src));
}
#define CP_COMMIT() asm volatile("cp.async.commit_group;" ::: "memory")
#define CP_WAIT1()  asm volatile("cp.async.wait_group 1;" ::: "memory")
#define CP_WAIT0()  asm volatile("cp.async.wait_group 0;" ::: "memory")

__device__ __forceinline__ void ldsm4(uint32_t& r0, uint32_t& r1, uint32_t& r2, uint32_t& r3,
                                      uint32_t a) {
    asm volatile("ldmatrix.sync.aligned.m8n8.x4.shared.b16 {%0,%1,%2,%3}, [%4];"
                 : "=r"(r0), "=r"(r1), "=r"(r2), "=r"(r3) : "r"(a));
}
__device__ __forceinline__ void ldsm4t(uint32_t& r0, uint32_t& r1, uint32_t& r2, uint32_t& r3,
                                       uint32_t a) {
    asm volatile("ldmatrix.sync.aligned.m8n8.x4.trans.shared.b16 {%0,%1,%2,%3}, [%4];"
                 : "=r"(r0), "=r"(r1), "=r"(r2), "=r"(r3) : "r"(a));
}
// fp16 MMA: D(16x8,f32) += A(16x16,f16) * B(16x8,f16)  [row.col]
__device__ __forceinline__ void mma_f16(float* d, const uint32_t* a, const uint32_t* b) {
    asm volatile(
        "mma.sync.aligned.m16n8k16.row.col.f32.f16.f16.f32 "
        "{%0,%1,%2,%3}, {%4,%5,%6,%7}, {%8,%9}, {%0,%1,%2,%3};"
        : "+f"(d[0]), "+f"(d[1]), "+f"(d[2]), "+f"(d[3])
        : "r"(a[0]), "r"(a[1]), "r"(a[2]), "r"(a[3]), "r"(b[0]), "r"(b[1]));
}

// ---- Shared-memory tile geometry ----
// A tile: 128 m-rows x 32 fp16, row stride 80B  (ldmatrix phase banks: 20r%32 distinct)
// B tile: 32 k-rows x 128 fp16, row stride 272B (ldmatrix phase banks: 68r%32=4r distinct)
#define AROWB 80
#define BROWB 272
#define A_STG_B (128*AROWB)                  // 10240 B
#define B_STG_B (32*BROWB)                   // 8704 B
#define SM_AS 512                            // after s_tok[128]
#define SM_BS (SM_AS + 2*A_STG_B)            // 512 + 20480 = 20992
#define GEMM_SMEM (SM_BS + 2*B_STG_B)        // + 17408 = 38400

// ==================== reset counters (graph replays) ====================
__global__ void zero_kernel() {
    int i = threadIdx.x;
    if (i < EDIM) { g_freq[i] = 0; g_cursor[i] = 0; g_psum[i] = 0.f; }
    if (i == 0) g_lsesq = 0.f;
}

// ==================== fp16 streaming conversion (no transpose) ====================
__global__ void convh_kernel(const float4* __restrict__ src, uint2* __restrict__ dst, int n4) {
    int i = blockIdx.x * 256 + threadIdx.x;
    if (i < n4) {
        float4 v = src[i];
        __half2 h01 = __floats2half2_rn(v.x, v.y);
        __half2 h23 = __floats2half2_rn(v.z, v.w);
        uint2 o;
        o.x = *(uint32_t*)&h01;
        o.y = *(uint32_t*)&h23;
        dst[i] = o;
    }
}

// ==================== router ====================
__global__ void router_kernel(const float* __restrict__ x,
                              const float* __restrict__ wr) {
    __shared__ float s_p[EDIM];
    __shared__ float s_lsesq;
    int tid = threadIdx.x;
    if (tid < EDIM) s_p[tid] = 0.f;
    if (tid == 0) s_lsesq = 0.f;
    __syncthreads();

    int t = blockIdx.x * 8 + (tid >> 5);
    int lane = tid & 31;

    float acc[8] = {0.f,0.f,0.f,0.f,0.f,0.f,0.f,0.f};
    const float* xp = x + (size_t)t * HDIM;
    for (int h = lane; h < HDIM; h += 32) {
        float xv = xp[h];
        float4 w0 = *(const float4*)(wr + h * 8);
        float4 w1 = *(const float4*)(wr + h * 8 + 4);
        acc[0] += xv * w0.x; acc[1] += xv * w0.y;
        acc[2] += xv * w0.z; acc[3] += xv * w0.w;
        acc[4] += xv * w1.x; acc[5] += xv * w1.y;
        acc[6] += xv * w1.z; acc[7] += xv * w1.w;
    }
#pragma unroll
    for (int e = 0; e < 8; e++)
#pragma unroll
        for (int o = 16; o > 0; o >>= 1)
            acc[e] += __shfl_down_sync(0xffffffffu, acc[e], o);

    if (lane == 0) {
        float m = acc[0];
#pragma unroll
        for (int e = 1; e < 8; e++) m = fmaxf(m, acc[e]);
        float ex[8], sum = 0.f;
#pragma unroll
        for (int e = 0; e < 8; e++) { ex[e] = expf(acc[e] - m); sum += ex[e]; }
        float inv = 1.f / sum;
        float lse = m + logf(sum);

        int i0 = 0;
#pragma unroll
        for (int e = 1; e < 8; e++) if (acc[e] > acc[i0]) i0 = e;
        int i1 = (i0 == 0) ? 1 : 0;
#pragma unroll
        for (int e = 0; e < 8; e++) if (e != i0 && acc[e] > acc[i1]) i1 = e;

        float d = expf(acc[i1] - acc[i0]);
        float g0 = 1.f / (1.f + d);
        float g1 = d / (1.f + d);

        g_eid[2 * t]     = i0;  g_eid[2 * t + 1]  = i1;
        g_gate[2 * t]    = g0;  g_gate[2 * t + 1] = g1;
        atomicAdd(&g_freq[i0], 1);
        atomicAdd(&g_freq[i1], 1);
#pragma unroll
        for (int e = 0; e < 8; e++) atomicAdd(&s_p[e], ex[e] * inv);
        atomicAdd(&s_lsesq, lse * lse);
    }
    __syncthreads();
    if (tid < EDIM) atomicAdd(&g_psum[tid], s_p[tid]);
    if (tid == 0)   atomicAdd(&g_lsesq, s_lsesq);
}

__global__ void scan_kernel() {
    if (threadIdx.x == 0) {
        int s = 0;
        for (int e = 0; e < EDIM; e++) { g_offsets[e] = s; s += g_freq[e]; }
        g_offsets[EDIM] = s;
    }
}

__global__ void scatter_kernel() {
    int r = blockIdx.x * blockDim.x + threadIdx.x;
    if (r < NROWS) {
        int e = g_eid[r];
        int pos = atomicAdd(&g_cursor[e], 1);
        g_list[g_offsets[e] + pos] = r;
    }
}

// ==================== tile loaders (128 threads, fp16, k-major B) ====================
// A: 128 rows x 32 fp16 (512 cp16). B: 32 k-rows x 128 n fp16 (512 cp16), straight from GMEM.
__device__ __forceinline__ void g1_load(const __half* __restrict__ w1,
                                        const int* s_tok,
                                        uint32_t as_u, uint32_t bs_u,
                                        int tid, int n0, int c, int st) {
    const int k0 = c * 32;
#pragma unroll
    for (int i = 0; i < 4; i++) {
        int idx = tid + i * 128;
        int row = idx >> 2, seg = idx & 3;
        const __half* src = g_xh + (size_t)s_tok[row] * HDIM + k0 + seg * 8;
        cp16(as_u + (uint32_t)(st * A_STG_B + row * AROWB + seg * 16), src);
    }
#pragma unroll
    for (int i = 0; i < 4; i++) {
        int idx = tid + i * 128;
        int kr = idx >> 4, j16 = idx & 15;
        int grp = j16 >> 2, cloc = (j16 & 3) * 8;
        int col = ((grp & 1) ? FDIM : 0) + n0 + (grp >> 1) * 32 + cloc;
        const __half* src = w1 + (size_t)(k0 + kr) * (2 * FDIM) + col;
        cp16(bs_u + (uint32_t)(st * B_STG_B + kr * BROWB + j16 * 16), src);
    }
    CP_COMMIT();
}

__device__ __forceinline__ void g2_load(const __half* __restrict__ w2,
                                        int off, int row0, int rlim,
                                        uint32_t as_u, uint32_t bs_u,
                                        int tid, int n1, int c, int st) {
    const int k0 = c * 32;
#pragma unroll
    for (int i = 0; i < 4; i++) {
        int idx = tid + i * 128;
        int row = idx >> 2, seg = idx & 3;
        int rr = (row < rlim) ? row : (rlim - 1);
        const __half* src = g_glu + (size_t)(off + row0 + rr) * FDIM + k0 + seg * 8;
        cp16(as_u + (uint32_t)(st * A_STG_B + row * AROWB + seg * 16), src);
    }
#pragma unroll
    for (int i = 0; i < 4; i++) {
        int idx = tid + i * 128;
        int kr = idx >> 4, j16 = idx & 15;
        const __half* src = w2 + (size_t)(k0 + kr) * HDIM + n1 + j16 * 8;
        cp16(bs_u + (uint32_t)(st * B_STG_B + kr * BROWB + j16 * 16), src);
    }
    CP_COMMIT();
}

// one K=32 chunk via ldmatrix: A x4 (row-major), B x4.trans (k-major in smem)
__device__ __forceinline__ void chunk_mma(uint32_t a_st, uint32_t b_st,
                                          int wm, int wn, int lane,
                                          float acc[4][8][4]) {
    const int l15 = lane & 15, l16 = lane >> 4;
#pragma unroll
    for (int ks = 0; ks < 2; ks++) {
        uint32_t af[4][4];
#pragma unroll
        for (int i = 0; i < 4; i++) {
            uint32_t addr = a_st + (uint32_t)((wm * 64 + i * 16 + l15) * AROWB + l16 * 16 + ks * 32);
            ldsm4(af[i][0], af[i][1], af[i][2], af[i][3], addr);
        }
        uint32_t bf[8][2];
#pragma unroll
        for (int fg = 0; fg < 4; fg++) {
            uint32_t addr = b_st + (uint32_t)((ks * 16 + l15) * BROWB + (wn * 64 + fg * 16 + l16 * 8) * 2);
            uint32_t r0, r1, r2, r3;
            ldsm4t(r0, r1, r2, r3, addr);
            bf[fg * 2][0] = r0;     bf[fg * 2][1] = r1;
            bf[fg * 2 + 1][0] = r2; bf[fg * 2 + 1][1] = r3;
        }
#pragma unroll
        for (int i = 0; i < 4; i++)
#pragma unroll
            for (int f = 0; f < 8; f++)
                mma_f16(acc[i][f], af[i], bf[f]);
    }
}

// ==================== GEMM1: x[tok] @ w_in[e], fused GLU ====================
// CTA tile 128 rows x (64 a-cols + 64 gv-cols). 4 warps of 64x64.
__global__ void __launch_bounds__(128) gemm1_mma(const __half* __restrict__ w1e) {
    const int e = blockIdx.z;
    const int cnt = g_freq[e];
    const int row0 = blockIdx.y * 128;
    if (row0 >= cnt) return;
    const int off = g_offsets[e];
    const int n0 = blockIdx.x * 64;

    extern __shared__ char smem[];
    int* s_tok = (int*)smem;
    const uint32_t su = smem_u32(smem);
    const uint32_t as_u = su + SM_AS, bs_u = su + SM_BS;

    const int tid = threadIdx.x;
    {
        int r = row0 + tid;
        s_tok[tid] = g_list[off + ((r < cnt) ? r : (cnt - 1))] >> 1;
    }
    __syncthreads();

    const __half* w1 = w1e + (size_t)e * HDIM * (2 * FDIM);

    const int lane = tid & 31, wid = tid >> 5;
    const int wm = wid & 1, wn = wid >> 1;
    const int g = lane >> 2, tq = lane & 3;

    float acc[4][8][4];
#pragma unroll
    for (int i = 0; i < 4; i++)
#pragma unroll
        for (int f = 0; f < 8; f++)
#pragma unroll
            for (int q = 0; q < 4; q++) acc[i][f][q] = 0.f;

    const int NCH = HDIM / 32;  // 32
    g1_load(w1, s_tok, as_u, bs_u, tid, n0, 0, 0);
    g1_load(w1, s_tok, as_u, bs_u, tid, n0, 1, 1);
    CP_WAIT1();
    __syncthreads();

    for (int c = 0; c < NCH; c++) {
        const int st = c & 1;
        chunk_mma(as_u + st * A_STG_B, bs_u + st * B_STG_B, wm, wn, lane, acc);
        __syncthreads();
        if (c + 2 < NCH) g1_load(w1, s_tok, as_u, bs_u, tid, n0, c + 2, st);
        if (c + 1 < NCH) {
            if (c + 2 < NCH) CP_WAIT1(); else CP_WAIT0();
            __syncthreads();
        }
    }

    // epilogue: GLU -> fp16 g_glu (warp wn pairs a-frag f with gv-frag f+4)
#pragma unroll
    for (int i = 0; i < 4; i++) {
        const int rbase = wm * 64 + i * 16 + g;
#pragma unroll
        for (int hr = 0; hr < 2; hr++) {
            const int r = rbase + hr * 8;
            if (row0 + r < cnt) {
                __half2* dst = (__half2*)(g_glu + (size_t)(off + row0 + r) * FDIM + n0 + wn * 32);
#pragma unroll
                for (int f = 0; f < 4; f++) {
                    float a0 = acc[i][f][hr * 2], a1 = acc[i][f][hr * 2 + 1];
                    float v0 = acc[i][f + 4][hr * 2], v1 = acc[i][f + 4][hr * 2 + 1];
                    float o0 = (a0 / (1.f + __expf(-a0))) * v0;
                    float o1 = (a1 / (1.f + __expf(-a1))) * v1;
                    dst[f * 4 + tq] = __floats2half2_rn(o0, o1);
                }
            }
        }
    }
}

// ==================== GEMM2: glu @ w_out[e], fused gate-scale scatter ====================
__global__ void __launch_bounds__(128) gemm2_mma(const __half* __restrict__ w2e) {
    const int e = blockIdx.z;
    const int cnt = g_freq[e];
    const int row0 = blockIdx.y * 128;
    if (row0 >= cnt) return;
    const int off = g_offsets[e];
    const int n1 = blockIdx.x * 128;
    const int rlim = cnt - row0;

    extern __shared__ char smem[];
    int* s_dst = (int*)smem;
    const uint32_t su = smem_u32(smem);
    const uint32_t as_u = su + SM_AS, bs_u = su + SM_BS;

    const int tid = threadIdx.x;
    {
        int r = row0 + tid;
        s_dst[tid] = g_list[off + ((r < cnt) ? r : (cnt - 1))];
    }
    __syncthreads();

    const __half* w2 = w2e + (size_t)e * FDIM * HDIM;

    const int lane = tid & 31, wid = tid >> 5;
    const int wm = wid & 1, wn = wid >> 1;
    const int g = lane >> 2, tq = lane & 3;

    float acc[4][8][4];
#pragma unroll
    for (int i = 0; i < 4; i++)
#pragma unroll
        for (int f = 0; f < 8; f++)
#pragma unroll
            for (int q = 0; q < 4; q++) acc[i][f][q] = 0.f;

    const int NCH = FDIM / 32;  // 64
    g2_load(w2, off, row0, rlim, as_u, bs_u, tid, n1, 0, 0);
    g2_load(w2, off, row0, rlim, as_u, bs_u, tid, n1, 1, 1);
    CP_WAIT1();
    __syncthreads();

    for (int c = 0; c < NCH; c++) {
        const int st = c & 1;
        chunk_mma(as_u + st * A_STG_B, bs_u + st * B_STG_B, wm, wn, lane, acc);
        __syncthreads();
        if (c + 2 < NCH) g2_load(w2, off, row0, rlim, as_u, bs_u, tid, n1, c + 2, st);
        if (c + 1 < NCH) {
            if (c + 2 < NCH) CP_WAIT1(); else CP_WAIT0();
            __syncthreads();
        }
    }

    // epilogue: scale by gate, scatter rows to g_pairs[dst]
#pragma unroll
    for (int i = 0; i < 4; i++) {
        const int rbase = wm * 64 + i * 16 + g;
#pragma unroll
        for (int hr = 0; hr < 2; hr++) {
            const int r = rbase + hr * 8;
            if (r < rlim) {
                const int dst = s_dst[r];
                const float gt = g_gate[dst];
                float* op = g_pairs + (size_t)dst * HDIM + n1 + wn * 64;
#pragma unroll
                for (int f = 0; f < 8; f++) {
                    float2 o;
                    o.x = acc[i][f][hr * 2] * gt;
                    o.y = acc[i][f][hr * 2 + 1] * gt;
                    *(float2*)(op + f * 8 + 2 * tq) = o;
                }
            }
        }
    }
}

// ==================== combine + loss ====================
__global__ void combine_kernel(float* __restrict__ out, const float* __restrict__ bias) {
    int i = blockIdx.x * blockDim.x + threadIdx.x;
    if (i < TDIM * HDIM / 4) {
        int t = i >> 8;
        int c4 = i & 255;
        const float4* p4 = (const float4*)g_pairs;
        float4 a = p4[(size_t)(2 * t) * 256 + c4];
        float4 b = p4[(size_t)(2 * t) * 256 + 256 + c4];
        float4 bs = ((const float4*)bias)[c4];
        float4 o;
        o.x = a.x + b.x + bs.x; o.y = a.y + b.y + bs.y;
        o.z = a.z + b.z + bs.z; o.w = a.w + b.w + bs.w;
        ((float4*)out)[i] = o;
    }
}

__global__ void loss_kernel(float* __restrict__ out, int out_size) {
    if (threadIdx.x == 0 && blockIdx.x == 0) {
        float s = 0.f;
        for (int e = 0; e < EDIM; e++) s += g_psum[e] * (float)g_freq[e];
        float loss = (float)EDIM * s / ((float)TDIM * (float)(TDIM * KSEL))
                   + 0.1f * g_lsesq / (float)TDIM;
        if (out_size > TDIM * HDIM) out[TDIM * HDIM] = loss;
    }
}

// ==================== launch ====================
extern "C" void kernel_launch(void* const* d_in, const int* in_sizes, int n_in,
                              void* d_out, int out_size) {
    const float* x        = (const float*)d_in[0];
    const float* w_router = (const float*)d_in[1];
    const float* w_in     = (const float*)d_in[2];
    const float* w_out    = (const float*)d_in[3];
    const float* bias     = (const float*)d_in[4];
    float* out = (float*)d_out;

    cudaFuncSetAttribute(gemm1_mma, cudaFuncAttributeMaxDynamicSharedMemorySize, GEMM_SMEM);
    cudaFuncSetAttribute(gemm2_mma, cudaFuncAttributeMaxDynamicSharedMemorySize, GEMM_SMEM);

    __half *xh_p, *w1h_p, *w2h_p;
    cudaGetSymbolAddress((void**)&xh_p, g_xh);
    cudaGetSymbolAddress((void**)&w1h_p, g_w1h);
    cudaGetSymbolAddress((void**)&w2h_p, g_w2h);

    zero_kernel<<<1, 32>>>();

    // streaming fp16 conversions (no transposes — ldmatrix.trans handles layout)
    {
        int n4x = TDIM * HDIM / 4;
        convh_kernel<<<(n4x + 255) / 256, 256>>>((const float4*)x, (uint2*)xh_p, n4x);
        int n4w1 = EDIM * HDIM * 2 * FDIM / 4;
        convh_kernel<<<(n4w1 + 255) / 256, 256>>>((const float4*)w_in, (uint2*)w1h_p, n4w1);
        int n4w2 = EDIM * FDIM * HDIM / 4;
        convh_kernel<<<(n4w2 + 255) / 256, 256>>>((const float4*)w_out, (uint2*)w2h_p, n4w2);
    }

    router_kernel<<<TDIM / 8, 256>>>(x, w_router);
    scan_kernel<<<1, 32>>>();
    scatter_kernel<<<NROWS / 256, 256>>>();

    gemm1_mma<<<dim3(FDIM / 64, TDIM / 128, EDIM), 128, GEMM_SMEM>>>(w1h_p);
    gemm2_mma<<<dim3(HDIM / 128, TDIM / 128, EDIM), 128, GEMM_SMEM>>>(w2h_p);

    combine_kernel<<<(TDIM * HDIM / 4 + 255) / 256, 256>>>(out, bias);
    loss_kernel<<<1, 32>>>(out, out_size);
}

// round 16
// speedup vs baseline: 1.6287x; 1.0187x over previous
#include <cuda_runtime.h>
#include <cuda_fp16.h>
#include <math.h>
#include <stdint.h>

// Problem constants
#define TDIM 4096          // B*S tokens
#define HDIM 1024          // hidden
#define EDIM 8             // experts
#define FDIM 2048          // ffn
#define KSEL 2             // top-k
#define NROWS (TDIM*KSEL)  // 8192 dispatch rows
#define GEMM_GRID 296      // 2 CTAs/SM x 148 SMs

// ==================== device scratch (allocation-free) ====================
__device__ __half g_xh[(size_t)TDIM * HDIM];              // x fp16 [T][H]
__device__ __half g_w1h[(size_t)EDIM * HDIM * 2 * FDIM];  // w_in  fp16 [E][H][2F]
__device__ __half g_w2h[(size_t)EDIM * FDIM * HDIM];      // w_out fp16 [E][F][H]
__device__ __half g_glu[(size_t)NROWS * FDIM];            // GLU acts fp16 (list order)
__device__ float  g_pairs[(size_t)NROWS * HDIM];          // expert outputs per (token,slot)
__device__ int   g_eid[NROWS];
__device__ float g_gate[NROWS];
__device__ int   g_list[NROWS];
__device__ int   g_freq[EDIM];
__device__ int   g_cursor[EDIM];
__device__ int   g_offsets[EDIM + 1];
__device__ int   g_w1off[EDIM + 1];   // gemm1 work-item prefix (last = total)
__device__ int   g_w2off[EDIM + 1];   // gemm2 work-item prefix (last = total)
__device__ float g_psum[EDIM];
__device__ float g_lsesq;

// ==================== PTX helpers (sm_80-baseline features only) ====================
__device__ __forceinline__ uint32_t smem_u32(const void* p) {
    uint32_t a;
    asm("{ .reg .u64 t; cvta.to.shared.u64 t, %1; cvt.u32.u64 %0, t; }" : "=r"(a) : "l"(p));
    return a;
}
__device__ __forceinline__ void cp16(uint32_t dst, const void* src) {
    asm volatile("cp.async.cg.shared.global [%0], [%1], 16;" :: "r"(dst), "l"(src));
}
#define CP_COMMIT() asm volatile("cp.async.commit_group;" ::: "memory")
#define CP_WAIT1()  asm volatile("cp.async.wait_group 1;" ::: "memory")
#define CP_WAIT0()  asm volatile("cp.async.wait_group 0;" ::: "memory")

__device__ __forceinline__ void ldsm4(uint32_t& r0, uint32_t& r1, uint32_t& r2, uint32_t& r3,
                                      uint32_t a) {
    asm volatile("ldmatrix.sync.aligned.m8n8.x4.shared.b16 {%0,%1,%2,%3}, [%4];"
                 : "=r"(r0), "=r"(r1), "=r"(r2), "=r"(r3) : "r"(a));
}
__device__ __forceinline__ void ldsm4t(uint32_t& r0, uint32_t& r1, uint32_t& r2, uint32_t& r3,
                                       uint32_t a) {
    asm volatile("ldmatrix.sync.aligned.m8n8.x4.trans.shared.b16 {%0,%1,%2,%3}, [%4];"
                 : "=r"(r0), "=r"(r1), "=r"(r2), "=r"(r3) : "r"(a));
}
// fp16 MMA: D(16x8,f32) += A(16x16,f16) * B(16x8,f16)  [row.col]
__device__ __forceinline__ void mma_f16(float* d, const uint32_t* a, const uint32_t* b) {
    asm volatile(
        "mma.sync.aligned.m16n8k16.row.col.f32.f16.f16.f32 "
        "{%0,%1,%2,%3}, {%4,%5,%6,%7}, {%8,%9}, {%0,%1,%2,%3};"
        : "+f"(d[0]), "+f"(d[1]), "+f"(d[2]), "+f"(d[3])
        : "r"(a[0]), "r"(a[1]), "r"(a[2]), "r"(a[3]), "r"(b[0]), "r"(b[1]));
}

// ---- Shared-memory tile geometry ----
#define AROWB 80                             // A row stride bytes (banks 20r%32 distinct)
#define BROWB 272                            // B row stride bytes (banks 4r distinct)
#define A_STG_B (128*AROWB)                  // 10240 B
#define B_STG_B (32*BROWB)                   // 8704 B
#define SM_AS 512                            // after s_tok[128]
#define SM_BS (SM_AS + 2*A_STG_B)            // 20992
#define GEMM_SMEM (SM_BS + 2*B_STG_B)        // 38400

// ==================== reset counters (graph replays) ====================
__global__ void zero_kernel() {
    int i = threadIdx.x;
    if (i < EDIM) { g_freq[i] = 0; g_cursor[i] = 0; g_psum[i] = 0.f; }
    if (i == 0) g_lsesq = 0.f;
}

// ==================== fp16 streaming conversion ====================
__global__ void convh_kernel(const float4* __restrict__ src, uint2* __restrict__ dst, int n4) {
    int i = blockIdx.x * 256 + threadIdx.x;
    if (i < n4) {
        float4 v = src[i];
        __half2 h01 = __floats2half2_rn(v.x, v.y);
        __half2 h23 = __floats2half2_rn(v.z, v.w);
        uint2 o;
        o.x = *(uint32_t*)&h01;
        o.y = *(uint32_t*)&h23;
        dst[i] = o;
    }
}

// ==================== router (also emits x as fp16) ====================
__global__ void router_kernel(const float* __restrict__ x,
                              const float* __restrict__ wr) {
    __shared__ float s_p[EDIM];
    __shared__ float s_lsesq;
    int tid = threadIdx.x;
    if (tid < EDIM) s_p[tid] = 0.f;
    if (tid == 0) s_lsesq = 0.f;
    __syncthreads();

    int t = blockIdx.x * 8 + (tid >> 5);
    int lane = tid & 31;

    float acc[8] = {0.f,0.f,0.f,0.f,0.f,0.f,0.f,0.f};
    const float* xp = x + (size_t)t * HDIM;
    __half* xh = g_xh + (size_t)t * HDIM;
    for (int h = lane; h < HDIM; h += 32) {
        float xv = xp[h];
        xh[h] = __float2half_rn(xv);            // fused fp16 conversion
        float4 w0 = *(const float4*)(wr + h * 8);
        float4 w1 = *(const float4*)(wr + h * 8 + 4);
        acc[0] += xv * w0.x; acc[1] += xv * w0.y;
        acc[2] += xv * w0.z; acc[3] += xv * w0.w;
        acc[4] += xv * w1.x; acc[5] += xv * w1.y;
        acc[6] += xv * w1.z; acc[7] += xv * w1.w;
    }
#pragma unroll
    for (int e = 0; e < 8; e++)
#pragma unroll
        for (int o = 16; o > 0; o >>= 1)
            acc[e] += __shfl_down_sync(0xffffffffu, acc[e], o);

    if (lane == 0) {
        float m = acc[0];
#pragma unroll
        for (int e = 1; e < 8; e++) m = fmaxf(m, acc[e]);
        float ex[8], sum = 0.f;
#pragma unroll
        for (int e = 0; e < 8; e++) { ex[e] = expf(acc[e] - m); sum += ex[e]; }
        float inv = 1.f / sum;
        float lse = m + logf(sum);

        int i0 = 0;
#pragma unroll
        for (int e = 1; e < 8; e++) if (acc[e] > acc[i0]) i0 = e;
        int i1 = (i0 == 0) ? 1 : 0;
#pragma unroll
        for (int e = 0; e < 8; e++) if (e != i0 && acc[e] > acc[i1]) i1 = e;

        float d = expf(acc[i1] - acc[i0]);
        float g0 = 1.f / (1.f + d);
        float g1 = d / (1.f + d);

        g_eid[2 * t]     = i0;  g_eid[2 * t + 1]  = i1;
        g_gate[2 * t]    = g0;  g_gate[2 * t + 1] = g1;
        atomicAdd(&g_freq[i0], 1);
        atomicAdd(&g_freq[i1], 1);
#pragma unroll
        for (int e = 0; e < 8; e++) atomicAdd(&s_p[e], ex[e] * inv);
        atomicAdd(&s_lsesq, lse * lse);
    }
    __syncthreads();
    if (tid < EDIM) atomicAdd(&g_psum[tid], s_p[tid]);
    if (tid == 0)   atomicAdd(&g_lsesq, s_lsesq);
}

// scan: token offsets + persistent-GEMM work-item tables
__global__ void scan_kernel() {
    if (threadIdx.x == 0) {
        int s = 0, s1 = 0, s2 = 0;
        for (int e = 0; e < EDIM; e++) {
            g_offsets[e] = s;
            g_w1off[e] = s1;
            g_w2off[e] = s2;
            int c = g_freq[e];
            int rt = (c + 127) >> 7;
            s += c;
            s1 += rt * (FDIM / 64);     // 32 n-tiles per row tile
            s2 += rt * (HDIM / 128);    // 8 n-tiles per row tile
        }
        g_offsets[EDIM] = s;
        g_w1off[EDIM] = s1;
        g_w2off[EDIM] = s2;
    }
}

__global__ void scatter_kernel() {
    int r = blockIdx.x * blockDim.x + threadIdx.x;
    if (r < NROWS) {
        int e = g_eid[r];
        int pos = atomicAdd(&g_cursor[e], 1);
        g_list[g_offsets[e] + pos] = r;
    }
}

// ==================== tile loaders (128 threads, fp16, k-major B) ====================
__device__ __forceinline__ void g1_load(const __half* __restrict__ w1,
                                        const int* s_tok,
                                        uint32_t as_u, uint32_t bs_u,
                                        int tid, int n0, int c, int st) {
    const int k0 = c * 32;
#pragma unroll
    for (int i = 0; i < 4; i++) {
        int idx = tid + i * 128;
        int row = idx >> 2, seg = idx & 3;
        const __half* src = g_xh + (size_t)s_tok[row] * HDIM + k0 + seg * 8;
        cp16(as_u + (uint32_t)(st * A_STG_B + row * AROWB + seg * 16), src);
    }
#pragma unroll
    for (int i = 0; i < 4; i++) {
        int idx = tid + i * 128;
        int kr = idx >> 4, j16 = idx & 15;
        int grp = j16 >> 2, cloc = (j16 & 3) * 8;
        int col = ((grp & 1) ? FDIM : 0) + n0 + (grp >> 1) * 32 + cloc;
        const __half* src = w1 + (size_t)(k0 + kr) * (2 * FDIM) + col;
        cp16(bs_u + (uint32_t)(st * B_STG_B + kr * BROWB + j16 * 16), src);
    }
    CP_COMMIT();
}

__device__ __forceinline__ void g2_load(const __half* __restrict__ w2,
                                        int off, int row0, int rlim,
                                        uint32_t as_u, uint32_t bs_u,
                                        int tid, int n1, int c, int st) {
    const int k0 = c * 32;
#pragma unroll
    for (int i = 0; i < 4; i++) {
        int idx = tid + i * 128;
        int row = idx >> 2, seg = idx & 3;
        int rr = (row < rlim) ? row : (rlim - 1);
        const __half* src = g_glu + (size_t)(off + row0 + rr) * FDIM + k0 + seg * 8;
        cp16(as_u + (uint32_t)(st * A_STG_B + row * AROWB + seg * 16), src);
    }
#pragma unroll
    for (int i = 0; i < 4; i++) {
        int idx = tid + i * 128;
        int kr = idx >> 4, j16 = idx & 15;
        const __half* src = w2 + (size_t)(k0 + kr) * HDIM + n1 + j16 * 8;
        cp16(bs_u + (uint32_t)(st * B_STG_B + kr * BROWB + j16 * 16), src);
    }
    CP_COMMIT();
}

// one K=32 chunk via ldmatrix
__device__ __forceinline__ void chunk_mma(uint32_t a_st, uint32_t b_st,
                                          int wm, int wn, int lane,
                                          float acc[4][8][4]) {
    const int l15 = lane & 15, l16 = lane >> 4;
#pragma unroll
    for (int ks = 0; ks < 2; ks++) {
        uint32_t af[4][4];
#pragma unroll
        for (int i = 0; i < 4; i++) {
            uint32_t addr = a_st + (uint32_t)((wm * 64 + i * 16 + l15) * AROWB + l16 * 16 + ks * 32);
            ldsm4(af[i][0], af[i][1], af[i][2], af[i][3], addr);
        }
        uint32_t bf[8][2];
#pragma unroll
        for (int fg = 0; fg < 4; fg++) {
            uint32_t addr = b_st + (uint32_t)((ks * 16 + l15) * BROWB + (wn * 64 + fg * 16 + l16 * 8) * 2);
            uint32_t r0, r1, r2, r3;
            ldsm4t(r0, r1, r2, r3, addr);
            bf[fg * 2][0] = r0;     bf[fg * 2][1] = r1;
            bf[fg * 2 + 1][0] = r2; bf[fg * 2 + 1][1] = r3;
        }
#pragma unroll
        for (int i = 0; i < 4; i++)
#pragma unroll
            for (int f = 0; f < 8; f++)
                mma_f16(acc[i][f], af[i], bf[f]);
    }
}

// ==================== GEMM1 (persistent): x[tok] @ w_in[e], fused GLU ====================
__global__ void __launch_bounds__(128) gemm1_mma(const __half* __restrict__ w1e) {
    extern __shared__ char smem[];
    int* s_tok = (int*)smem;
    const uint32_t su = smem_u32(smem);
    const uint32_t as_u = su + SM_AS, bs_u = su + SM_BS;

    const int tid = threadIdx.x;
    const int lane = tid & 31, wid = tid >> 5;
    const int wm = wid & 1, wn = wid >> 1;
    const int g = lane >> 2, tq = lane & 3;

    int woff[EDIM + 1];
#pragma unroll
    for (int k = 0; k <= EDIM; k++) woff[k] = g_w1off[k];
    const int tot = woff[EDIM];

    for (int w = blockIdx.x; w < tot; w += (int)gridDim.x) {
        int e = 0;
#pragma unroll
        for (int k = 1; k < EDIM; k++) e = (w >= woff[k]) ? k : e;
        const int local = w - woff[e];
        const int row0 = (local >> 5) * 128;
        const int n0 = (local & 31) << 6;
        const int cnt = g_freq[e];
        const int off = g_offsets[e];

        __syncthreads();
        {
            int r = row0 + tid;
            s_tok[tid] = g_list[off + ((r < cnt) ? r : (cnt - 1))] >> 1;
        }
        __syncthreads();

        const __half* w1 = w1e + (size_t)e * HDIM * (2 * FDIM);

        float acc[4][8][4];
#pragma unroll
        for (int i = 0; i < 4; i++)
#pragma unroll
            for (int f = 0; f < 8; f++)
#pragma unroll
                for (int q = 0; q < 4; q++) acc[i][f][q] = 0.f;

        const int NCH = HDIM / 32;  // 32
        g1_load(w1, s_tok, as_u, bs_u, tid, n0, 0, 0);
        g1_load(w1, s_tok, as_u, bs_u, tid, n0, 1, 1);
        CP_WAIT1();
        __syncthreads();

        for (int c = 0; c < NCH; c++) {
            const int st = c & 1;
            chunk_mma(as_u + st * A_STG_B, bs_u + st * B_STG_B, wm, wn, lane, acc);
            __syncthreads();
            if (c + 2 < NCH) g1_load(w1, s_tok, as_u, bs_u, tid, n0, c + 2, st);
            if (c + 1 < NCH) {
                if (c + 2 < NCH) CP_WAIT1(); else CP_WAIT0();
                __syncthreads();
            }
        }

        // epilogue: GLU -> fp16 g_glu
#pragma unroll
        for (int i = 0; i < 4; i++) {
            const int rbase = wm * 64 + i * 16 + g;
#pragma unroll
            for (int hr = 0; hr < 2; hr++) {
                const int r = rbase + hr * 8;
                if (row0 + r < cnt) {
                    __half2* dst = (__half2*)(g_glu + (size_t)(off + row0 + r) * FDIM + n0 + wn * 32);
#pragma unroll
                    for (int f = 0; f < 4; f++) {
                        float a0 = acc[i][f][hr * 2], a1 = acc[i][f][hr * 2 + 1];
                        float v0 = acc[i][f + 4][hr * 2], v1 = acc[i][f + 4][hr * 2 + 1];
                        float o0 = (a0 / (1.f + __expf(-a0))) * v0;
                        float o1 = (a1 / (1.f + __expf(-a1))) * v1;
                        dst[f * 4 + tq] = __floats2half2_rn(o0, o1);
                    }
                }
            }
        }
    }
}

// ==================== GEMM2 (persistent): glu @ w_out[e], gate-scale scatter ====================
__global__ void __launch_bounds__(128) gemm2_mma(const __half* __restrict__ w2e) {
    extern __shared__ char smem[];
    int* s_dst = (int*)smem;
    const uint32_t su = smem_u32(smem);
    const uint32_t as_u = su + SM_AS, bs_u = su + SM_BS;

    const int tid = threadIdx.x;
    const int lane = tid & 31, wid = tid >> 5;
    const int wm = wid & 1, wn = wid >> 1;
    const int g = lane >> 2, tq = lane & 3;

    int woff[EDIM + 1];
#pragma unroll
    for (int k = 0; k <= EDIM; k++) woff[k] = g_w2off[k];
    const int tot = woff[EDIM];

    for (int w = blockIdx.x; w < tot; w += (int)gridDim.x) {
        int e = 0;
#pragma unroll
        for (int k = 1; k < EDIM; k++) e = (w >= woff[k]) ? k : e;
        const int local = w - woff[e];
        const int row0 = (local >> 3) * 128;
        const int n1 = (local & 7) << 7;
        const int cnt = g_freq[e];
        const int off = g_offsets[e];
        const int rlim = cnt - row0;

        __syncthreads();
        {
            int r = row0 + tid;
            s_dst[tid] = g_list[off + ((r < cnt) ? r : (cnt - 1))];
        }
        __syncthreads();

        const __half* w2 = w2e + (size_t)e * FDIM * HDIM;

        float acc[4][8][4];
#pragma unroll
        for (int i = 0; i < 4; i++)
#pragma unroll
            for (int f = 0; f < 8; f++)
#pragma unroll
                for (int q = 0; q < 4; q++) acc[i][f][q] = 0.f;

        const int NCH = FDIM / 32;  // 64
        g2_load(w2, off, row0, rlim, as_u, bs_u, tid, n1, 0, 0);
        g2_load(w2, off, row0, rlim, as_u, bs_u, tid, n1, 1, 1);
        CP_WAIT1();
        __syncthreads();

        for (int c = 0; c < NCH; c++) {
            const int st = c & 1;
            chunk_mma(as_u + st * A_STG_B, bs_u + st * B_STG_B, wm, wn, lane, acc);
            __syncthreads();
            if (c + 2 < NCH) g2_load(w2, off, row0, rlim, as_u, bs_u, tid, n1, c + 2, st);
            if (c + 1 < NCH) {
                if (c + 2 < NCH) CP_WAIT1(); else CP_WAIT0();
                __syncthreads();
            }
        }

        // epilogue: scale by gate, scatter rows to g_pairs[dst]
#pragma unroll
        for (int i = 0; i < 4; i++) {
            const int rbase = wm * 64 + i * 16 + g;
#pragma unroll
            for (int hr = 0; hr < 2; hr++) {
                const int r = rbase + hr * 8;
                if (r < rlim) {
                    const int dst = s_dst[r];
                    const float gt = g_gate[dst];
                    float* op = g_pairs + (size_t)dst * HDIM + n1 + wn * 64;
#pragma unroll
                    for (int f = 0; f < 8; f++) {
                        float2 o;
                        o.x = acc[i][f][hr * 2] * gt;
                        o.y = acc[i][f][hr * 2 + 1] * gt;
                        *(float2*)(op + f * 8 + 2 * tq) = o;
                    }
                }
            }
        }
    }
}

// ==================== combine + loss ====================
__global__ void combine_kernel(float* __restrict__ out, const float* __restrict__ bias) {
    int i = blockIdx.x * blockDim.x + threadIdx.x;
    if (i < TDIM * HDIM / 4) {
        int t = i >> 8;
        int c4 = i & 255;
        const float4* p4 = (const float4*)g_pairs;
        float4 a = p4[(size_t)(2 * t) * 256 + c4];
        float4 b = p4[(size_t)(2 * t) * 256 + 256 + c4];
        float4 bs = ((const float4*)bias)[c4];
        float4 o;
        o.x = a.x + b.x + bs.x; o.y = a.y + b.y + bs.y;
        o.z = a.z + b.z + bs.z; o.w = a.w + b.w + bs.w;
        ((float4*)out)[i] = o;
    }
}

__global__ void loss_kernel(float* __restrict__ out, int out_size) {
    if (threadIdx.x == 0 && blockIdx.x == 0) {
        float s = 0.f;
        for (int e = 0; e < EDIM; e++) s += g_psum[e] * (float)g_freq[e];
        float loss = (float)EDIM * s / ((float)TDIM * (float)(TDIM * KSEL))
                   + 0.1f * g_lsesq / (float)TDIM;
        if (out_size > TDIM * HDIM) out[TDIM * HDIM] = loss;
    }
}

// ==================== launch ====================
extern "C" void kernel_launch(void* const* d_in, const int* in_sizes, int n_in,
                              void* d_out, int out_size) {
    const float* x        = (const float*)d_in[0];
    const float* w_router = (const float*)d_in[1];
    const float* w_in     = (const float*)d_in[2];
    const float* w_out    = (const float*)d_in[3];
    const float* bias     = (const float*)d_in[4];
    float* out = (float*)d_out;

    // one-time handles (created on the non-captured correctness call; no device mem)
    static cudaStream_t s2 = nullptr;
    static cudaEvent_t evFork = nullptr, evW1 = nullptr, evW2 = nullptr;
    if (s2 == nullptr) {
        cudaStreamCreateWithFlags(&s2, cudaStreamNonBlocking);
        cudaEventCreateWithFlags(&evFork, cudaEventDisableTiming);
        cudaEventCreateWithFlags(&evW1, cudaEventDisableTiming);
        cudaEventCreateWithFlags(&evW2, cudaEventDisableTiming);
    }

    cudaFuncSetAttribute(gemm1_mma, cudaFuncAttributeMaxDynamicSharedMemorySize, GEMM_SMEM);
    cudaFuncSetAttribute(gemm2_mma, cudaFuncAttributeMaxDynamicSharedMemorySize, GEMM_SMEM);

    __half *w1h_p, *w2h_p;
    cudaGetSymbolAddress((void**)&w1h_p, g_w1h);
    cudaGetSymbolAddress((void**)&w2h_p, g_w2h);

    zero_kernel<<<1, 32>>>();

    // fork: weight fp16 conversions on side stream, overlapped with router/scatter/gemm1
    cudaEventRecord(evFork, 0);
    cudaStreamWaitEvent(s2, evFork, 0);
    {
        int n4w1 = EDIM * HDIM * 2 * FDIM / 4;
        convh_kernel<<<(n4w1 + 255) / 256, 256, 0, s2>>>((const float4*)w_in, (uint2*)w1h_p, n4w1);
        cudaEventRecord(evW1, s2);
        int n4w2 = EDIM * FDIM * HDIM / 4;
        convh_kernel<<<(n4w2 + 255) / 256, 256, 0, s2>>>((const float4*)w_out, (uint2*)w2h_p, n4w2);
        cudaEventRecord(evW2, s2);
    }

    // main stream: router (+x fp16), dispatch build
    router_kernel<<<TDIM / 8, 256>>>(x, w_router);
    scan_kernel<<<1, 32>>>();
    scatter_kernel<<<NROWS / 256, 256>>>();

    cudaStreamWaitEvent(0, evW1, 0);   // join: gemm1 needs w1h
    gemm1_mma<<<GEMM_GRID, 128, GEMM_SMEM>>>(w1h_p);

    cudaStreamWaitEvent(0, evW2, 0);   // join: gemm2 needs w2h
    gemm2_mma<<<GEMM_GRID, 128, GEMM_SMEM>>>(w2h_p);

    combine_kernel<<<(TDIM * HDIM / 4 + 255) / 256, 256>>>(out, bias);
    loss_kernel<<<1, 32>>>(out, out_size);
}